// round 2
// baseline (speedup 1.0000x reference)
#include <cuda_runtime.h>
#include <math.h>

#define BB 2
#define TT 4096
#define DD 768
#define HH 12
#define DKK 64
#define MROWS (BB*TT)          // 8192
#define THREEDD (3*DD)         // 2304

// Scratch (static device allocations are allowed; runtime allocs are not)
__device__ float g_qkv[(size_t)MROWS * THREEDD];   // [8192, 2304]
__device__ float g_attn[(size_t)MROWS * DD];       // [8192, 768]

// ---------------------------------------------------------------------------
// SGEMM + bias: C[M,N] = A[M,K] @ W[K,N] + bias[N]
// 64x64 tile, BK=16, 256 threads, 4x4 micro-tile, float4 shared reads.
// All dims are multiples of 64/16 here, so no bounds checks.
// ---------------------------------------------------------------------------
__global__ __launch_bounds__(256) void sgemm_bias_kernel(
    const float* __restrict__ A, const float* __restrict__ W,
    const float* __restrict__ bias, float* __restrict__ C,
    int Mdim, int Ndim, int Kdim)
{
    __shared__ __align__(16) float As[16][68];   // [k][m], padded
    __shared__ __align__(16) float Bs[16][68];   // [k][n], padded

    const int tid = threadIdx.x;
    const int tx = tid & 15;
    const int ty = tid >> 4;
    const int m0 = blockIdx.y * 64;
    const int n0 = blockIdx.x * 64;

    float acc[4][4] = {};

    for (int k0 = 0; k0 < Kdim; k0 += 16) {
        // A tile 64x16 -> As[k][m] (transposed store)
        #pragma unroll
        for (int t = 0; t < 4; ++t) {
            int idx = tid + t * 256;
            int k = idx & 15;
            int m = idx >> 4;
            As[k][m] = A[(size_t)(m0 + m) * Kdim + k0 + k];
        }
        // W tile 16x64 -> Bs[k][n] (natural, coalesced)
        #pragma unroll
        for (int t = 0; t < 4; ++t) {
            int idx = tid + t * 256;
            int n = idx & 63;
            int k = idx >> 6;
            Bs[k][n] = W[(size_t)(k0 + k) * Ndim + n0 + n];
        }
        __syncthreads();

        #pragma unroll
        for (int kk = 0; kk < 16; ++kk) {
            float4 av = *(const float4*)&As[kk][ty * 4];
            float4 bv = *(const float4*)&Bs[kk][tx * 4];
            float a[4] = {av.x, av.y, av.z, av.w};
            float b[4] = {bv.x, bv.y, bv.z, bv.w};
            #pragma unroll
            for (int i = 0; i < 4; ++i)
                #pragma unroll
                for (int j = 0; j < 4; ++j)
                    acc[i][j] = fmaf(a[i], b[j], acc[i][j]);
        }
        __syncthreads();
    }

    float4 bv = *(const float4*)&bias[n0 + tx * 4];
    #pragma unroll
    for (int i = 0; i < 4; ++i) {
        int row = m0 + ty * 4 + i;
        float4 out;
        out.x = acc[i][0] + bv.x;
        out.y = acc[i][1] + bv.y;
        out.z = acc[i][2] + bv.z;
        out.w = acc[i][3] + bv.w;
        *(float4*)&C[(size_t)row * Ndim + n0 + tx * 4] = out;
    }
}

// ---------------------------------------------------------------------------
// Causal flash attention.
// grid = (T/64, H, B), block = 256 (16x16), dynamic smem = 51200 B
//   Qs : [64][68]  Q tile transposed  (d-major)
//   KPs: [64][68]  K tile transposed, later aliased as P transposed ([c][r])
//   Vs : [64][64]  V tile natural
// Each thread owns a 4x4 block of the 64x64 S tile AND the same 4 rows x
// 4 dk-cols of the O accumulator, so softmax row state stays in registers.
// ---------------------------------------------------------------------------
__global__ __launch_bounds__(256) void attn_kernel(
    const float* __restrict__ qkv, float* __restrict__ out)
{
    extern __shared__ __align__(16) float sm[];
    float* Qs  = sm;                 // 64*68 floats
    float* KPs = sm + 64 * 68;       // 64*68 floats
    float* Vs  = sm + 2 * 64 * 68;   // 64*64 floats

    const int tid = threadIdx.x;
    const int tx = tid & 15;
    const int ty = tid >> 4;
    const int qt = blockIdx.x;
    const int h  = blockIdx.y;
    const int b  = blockIdx.z;

    const size_t rs = THREEDD;  // row stride in qkv
    const float* qbase = qkv + (size_t)b * TT * rs + h * DKK;
    const float* kbase = qbase + DD;
    const float* vbase = qbase + 2 * DD;

    // Load Q tile transposed: Qs[d][r] = Q[qt*64+r][d]
    #pragma unroll
    for (int t = 0; t < 16; ++t) {
        int idx = tid + t * 256;
        int r = idx >> 6;
        int d = idx & 63;
        Qs[d * 68 + r] = qbase[(size_t)(qt * 64 + r) * rs + d];
    }

    float m_prev[4], l_run[4], o[4][4] = {};
    #pragma unroll
    for (int i = 0; i < 4; ++i) { m_prev[i] = -1e30f; l_run[i] = 0.f; }

    const float scale = 0.125f;  // 1/sqrt(64)

    for (int kt = 0; kt <= qt; ++kt) {
        __syncthreads();  // previous iter done with KPs/Vs
        #pragma unroll
        for (int t = 0; t < 16; ++t) {
            int idx = tid + t * 256;
            int r = idx >> 6;
            int d = idx & 63;
            size_t g = (size_t)(kt * 64 + r) * rs + d;
            KPs[d * 68 + r] = kbase[g];   // K transposed
            Vs[r * 64 + d]  = vbase[g];   // V natural
        }
        __syncthreads();

        // S = Q @ K^T  (64x64x64)
        float s[4][4] = {};
        #pragma unroll
        for (int d = 0; d < 64; ++d) {
            float4 av = *(const float4*)&Qs[d * 68 + ty * 4];
            float4 bv = *(const float4*)&KPs[d * 68 + tx * 4];
            float a[4] = {av.x, av.y, av.z, av.w};
            float bb[4] = {bv.x, bv.y, bv.z, bv.w};
            #pragma unroll
            for (int i = 0; i < 4; ++i)
                #pragma unroll
                for (int j = 0; j < 4; ++j)
                    s[i][j] = fmaf(a[i], bb[j], s[i][j]);
        }

        // scale + causal mask (only the diagonal tile needs masking)
        #pragma unroll
        for (int i = 0; i < 4; ++i)
            #pragma unroll
            for (int j = 0; j < 4; ++j)
                s[i][j] *= scale;
        if (kt == qt) {
            int qrow0 = ty * 4, kcol0 = tx * 4;
            #pragma unroll
            for (int i = 0; i < 4; ++i)
                #pragma unroll
                for (int j = 0; j < 4; ++j)
                    if (kcol0 + j > qrow0 + i) s[i][j] = -1e30f;
        }

        // online softmax: row reductions across tx (16 lanes, same ty)
        float mt[4], p[4][4], rsum[4], corr[4];
        #pragma unroll
        for (int i = 0; i < 4; ++i) {
            mt[i] = fmaxf(fmaxf(s[i][0], s[i][1]), fmaxf(s[i][2], s[i][3]));
        }
        #pragma unroll
        for (int off = 8; off > 0; off >>= 1)
            #pragma unroll
            for (int i = 0; i < 4; ++i)
                mt[i] = fmaxf(mt[i], __shfl_xor_sync(0xffffffffu, mt[i], off, 16));

        #pragma unroll
        for (int i = 0; i < 4; ++i) {
            float m_new = fmaxf(m_prev[i], mt[i]);
            rsum[i] = 0.f;
            #pragma unroll
            for (int j = 0; j < 4; ++j) {
                p[i][j] = __expf(s[i][j] - m_new);
                rsum[i] += p[i][j];
            }
            corr[i] = __expf(m_prev[i] - m_new);
            m_prev[i] = m_new;
        }
        #pragma unroll
        for (int off = 8; off > 0; off >>= 1)
            #pragma unroll
            for (int i = 0; i < 4; ++i)
                rsum[i] += __shfl_xor_sync(0xffffffffu, rsum[i], off, 16);

        #pragma unroll
        for (int i = 0; i < 4; ++i) {
            l_run[i] = l_run[i] * corr[i] + rsum[i];
            #pragma unroll
            for (int j = 0; j < 4; ++j)
                o[i][j] *= corr[i];
        }

        __syncthreads();  // everyone done reading KPs as K
        // write P transposed: KPs[c][r] = P[r][c]
        #pragma unroll
        for (int i = 0; i < 4; ++i)
            #pragma unroll
            for (int j = 0; j < 4; ++j)
                KPs[(tx * 4 + j) * 68 + ty * 4 + i] = p[i][j];
        __syncthreads();

        // O += P @ V  (64x64x64)
        #pragma unroll
        for (int sidx = 0; sidx < 64; ++sidx) {
            float4 av = *(const float4*)&KPs[sidx * 68 + ty * 4];
            float4 bv = *(const float4*)&Vs[sidx * 64 + tx * 4];
            float a[4] = {av.x, av.y, av.z, av.w};
            float bb[4] = {bv.x, bv.y, bv.z, bv.w};
            #pragma unroll
            for (int i = 0; i < 4; ++i)
                #pragma unroll
                for (int j = 0; j < 4; ++j)
                    o[i][j] = fmaf(a[i], bb[j], o[i][j]);
        }
    }

    // epilogue: out[b, qt*64+r, h*64+dk] = o / l
    #pragma unroll
    for (int i = 0; i < 4; ++i) {
        int row = qt * 64 + ty * 4 + i;
        float inv = 1.0f / l_run[i];
        float4 ov;
        ov.x = o[i][0] * inv;
        ov.y = o[i][1] * inv;
        ov.z = o[i][2] * inv;
        ov.w = o[i][3] * inv;
        *(float4*)&out[((size_t)b * TT + row) * DD + h * DKK + tx * 4] = ov;
    }
}

// ---------------------------------------------------------------------------
extern "C" void kernel_launch(void* const* d_in, const int* in_sizes, int n_in,
                              void* d_out, int out_size)
{
    const float* x      = (const float*)d_in[0];   // [2,4096,768]
    const float* W_qkv  = (const float*)d_in[1];   // [768,2304]
    const float* b_qkv  = (const float*)d_in[2];   // [2304]
    const float* W_proj = (const float*)d_in[3];   // [768,768]
    const float* b_proj = (const float*)d_in[4];   // [768]
    float* out = (float*)d_out;

    float* qkv_scratch;
    float* attn_scratch;
    cudaGetSymbolAddress((void**)&qkv_scratch, g_qkv);
    cudaGetSymbolAddress((void**)&attn_scratch, g_attn);

    // 1) QKV projection: [8192,768] @ [768,2304] + bias
    {
        dim3 grid(THREEDD / 64, MROWS / 64);
        sgemm_bias_kernel<<<grid, 256>>>(x, W_qkv, b_qkv, qkv_scratch,
                                         MROWS, THREEDD, DD);
    }

    // 2) Causal flash attention
    {
        const int smem = (2 * 64 * 68 + 64 * 64) * (int)sizeof(float); // 51200
        cudaFuncSetAttribute(attn_kernel,
                             cudaFuncAttributeMaxDynamicSharedMemorySize, smem);
        dim3 grid(TT / 64, HH, BB);
        attn_kernel<<<grid, 256, smem>>>(qkv_scratch, attn_scratch);
    }

    // 3) Output projection: [8192,768] @ [768,768] + bias
    {
        dim3 grid(DD / 64, MROWS / 64);
        sgemm_bias_kernel<<<grid, 256>>>(attn_scratch, W_proj, b_proj, out,
                                         MROWS, DD, DD);
    }
}

// round 4
// speedup vs baseline: 1.1310x; 1.1310x over previous
#include <cuda_runtime.h>
#include <math.h>

#define BB 2
#define TT 4096
#define DD 768
#define HH 12
#define DKK 64
#define MROWS (BB*TT)          // 8192
#define THREEDD (3*DD)         // 2304

__device__ float g_qkv[(size_t)MROWS * THREEDD];   // [8192, 2304]
__device__ float g_attn[(size_t)MROWS * DD];       // [8192, 768]

// ---------------------------------------------------------------------------
// SGEMM + bias: C[M,N] = A[M,K] @ W[K,N] + bias[N]
// 128x128 tile, BK=16, 256 threads, 8x8 micro-tile, double-buffered smem.
// M,N multiples of 128; K multiple of 16.
// ---------------------------------------------------------------------------
__global__ __launch_bounds__(256, 2) void sgemm_bias_128(
    const float* __restrict__ A, const float* __restrict__ W,
    const float* __restrict__ bias, float* __restrict__ C,
    int Ndim, int Kdim)
{
    __shared__ __align__(16) float As[2][16 * 132];
    __shared__ __align__(16) float Bs[2][16 * 132];

    const int tid = threadIdx.x;
    const int tx = tid & 15;
    const int ty = tid >> 4;
    const int m0 = blockIdx.y * 128;
    const int n0 = blockIdx.x * 128;

    const int ar = tid >> 2;          // 0..63 (rows ar, ar+64)
    const int ak = (tid & 3) * 4;     // k offset 0,4,8,12
    const int br = tid >> 5;          // 0..7 (rows br, br+8)
    const int bc = (tid & 31) * 4;    // 0..124

    const float* Aptr = A + (size_t)(m0 + ar) * Kdim + ak;
    const float* Wptr = W + (size_t)br * Ndim + n0 + bc;

    float4 a0r = *(const float4*)(Aptr);
    float4 a1r = *(const float4*)(Aptr + (size_t)64 * Kdim);
    float4 b0r = *(const float4*)(Wptr);
    float4 b1r = *(const float4*)(Wptr + (size_t)8 * Ndim);

    {
        float* as = As[0];
        float* bs = Bs[0];
        as[(ak + 0) * 132 + ar] = a0r.x;
        as[(ak + 1) * 132 + ar] = a0r.y;
        as[(ak + 2) * 132 + ar] = a0r.z;
        as[(ak + 3) * 132 + ar] = a0r.w;
        as[(ak + 0) * 132 + ar + 64] = a1r.x;
        as[(ak + 1) * 132 + ar + 64] = a1r.y;
        as[(ak + 2) * 132 + ar + 64] = a1r.z;
        as[(ak + 3) * 132 + ar + 64] = a1r.w;
        *(float4*)&bs[br * 132 + bc] = b0r;
        *(float4*)&bs[(br + 8) * 132 + bc] = b1r;
    }
    __syncthreads();

    float acc[8][8] = {};
    const int nk = Kdim >> 4;

    for (int kb = 0; kb < nk; ++kb) {
        const float* as = As[kb & 1];
        const float* bs = Bs[kb & 1];

        if (kb + 1 < nk) {
            const float* Ap = Aptr + (size_t)(kb + 1) * 16;
            a0r = *(const float4*)Ap;
            a1r = *(const float4*)(Ap + (size_t)64 * Kdim);
            const float* Wp = Wptr + (size_t)(kb + 1) * 16 * Ndim;
            b0r = *(const float4*)Wp;
            b1r = *(const float4*)(Wp + (size_t)8 * Ndim);
        }

        #pragma unroll
        for (int kk = 0; kk < 16; ++kk) {
            float4 av0 = *(const float4*)&as[kk * 132 + ty * 8];
            float4 av1 = *(const float4*)&as[kk * 132 + ty * 8 + 4];
            float4 bv0 = *(const float4*)&bs[kk * 132 + tx * 8];
            float4 bv1 = *(const float4*)&bs[kk * 132 + tx * 8 + 4];
            float a[8] = {av0.x, av0.y, av0.z, av0.w, av1.x, av1.y, av1.z, av1.w};
            float bvals[8] = {bv0.x, bv0.y, bv0.z, bv0.w, bv1.x, bv1.y, bv1.z, bv1.w};
            #pragma unroll
            for (int i = 0; i < 8; ++i)
                #pragma unroll
                for (int j = 0; j < 8; ++j)
                    acc[i][j] = fmaf(a[i], bvals[j], acc[i][j]);
        }

        if (kb + 1 < nk) {
            float* asn = As[(kb + 1) & 1];
            float* bsn = Bs[(kb + 1) & 1];
            asn[(ak + 0) * 132 + ar] = a0r.x;
            asn[(ak + 1) * 132 + ar] = a0r.y;
            asn[(ak + 2) * 132 + ar] = a0r.z;
            asn[(ak + 3) * 132 + ar] = a0r.w;
            asn[(ak + 0) * 132 + ar + 64] = a1r.x;
            asn[(ak + 1) * 132 + ar + 64] = a1r.y;
            asn[(ak + 2) * 132 + ar + 64] = a1r.z;
            asn[(ak + 3) * 132 + ar + 64] = a1r.w;
            *(float4*)&bsn[br * 132 + bc] = b0r;
            *(float4*)&bsn[(br + 8) * 132 + bc] = b1r;
        }
        __syncthreads();
    }

    float4 bi0 = *(const float4*)&bias[n0 + tx * 8];
    float4 bi1 = *(const float4*)&bias[n0 + tx * 8 + 4];
    #pragma unroll
    for (int i = 0; i < 8; ++i) {
        int row = m0 + ty * 8 + i;
        float4 o0, o1;
        o0.x = acc[i][0] + bi0.x; o0.y = acc[i][1] + bi0.y;
        o0.z = acc[i][2] + bi0.z; o0.w = acc[i][3] + bi0.w;
        o1.x = acc[i][4] + bi1.x; o1.y = acc[i][5] + bi1.y;
        o1.z = acc[i][6] + bi1.z; o1.w = acc[i][7] + bi1.w;
        *(float4*)&C[(size_t)row * Ndim + n0 + tx * 8] = o0;
        *(float4*)&C[(size_t)row * Ndim + n0 + tx * 8 + 4] = o1;
    }
}

// ---------------------------------------------------------------------------
// Causal flash attention. Q tile 128 x K tile 128, 256 threads, 8x8 S-microtile.
// smem (floats):
//   Qs   [64][132]        Q transposed (d-major)            [0, 8448)
//   KsPT region           Ks [64][132] then PT 128x128 swz  [8448, 24832)
//   Vs   [128][68]        V natural                         [24832, 33536)
// PT physical layout: PT[s][r4block] at s*128 + (r4 ^ (((s>>3)&7)*4))
// ---------------------------------------------------------------------------
__global__ __launch_bounds__(256, 1) void attn_kernel(
    const float* __restrict__ qkv, float* __restrict__ out)
{
    extern __shared__ __align__(16) float sm[];
    float* Qs   = sm;
    float* KsPT = sm + 8448;
    float* Vs   = sm + 8448 + 16384;

    const int tid = threadIdx.x;
    const int tx = tid & 15;
    const int ty = tid >> 4;
    const int qt = (int)gridDim.x - 1 - (int)blockIdx.x;  // heavy tiles first
    const int h  = blockIdx.y;
    const int b  = blockIdx.z;

    const size_t rs = THREEDD;
    const float* qbase = qkv + (size_t)b * TT * rs + h * DKK;
    const float* kbase = qbase + DD;
    const float* vbase = qbase + 2 * DD;

    const int lf = tid >> 4;   // 0..15 float4 column (d)
    const int lr = tid & 15;   // row base

    // Load Q tile transposed: Qs[d][r]
    #pragma unroll
    for (int u = 0; u < 8; ++u) {
        int r = lr + 16 * u;
        float4 v = *(const float4*)&qbase[(size_t)(qt * 128 + r) * rs + lf * 4];
        Qs[(lf * 4 + 0) * 132 + r] = v.x;
        Qs[(lf * 4 + 1) * 132 + r] = v.y;
        Qs[(lf * 4 + 2) * 132 + r] = v.z;
        Qs[(lf * 4 + 3) * 132 + r] = v.w;
    }

    float m_prev[8], l_run[8], o[8][4];
    #pragma unroll
    for (int i = 0; i < 8; ++i) {
        m_prev[i] = -1e30f;
        l_run[i] = 0.f;
        o[i][0] = o[i][1] = o[i][2] = o[i][3] = 0.f;
    }

    const float scale = 0.125f;  // 1/sqrt(64)

    for (int kt = 0; kt <= qt; ++kt) {
        __syncthreads();  // prior PV done: KsPT/Vs reusable
        #pragma unroll
        for (int u = 0; u < 8; ++u) {
            int r = lr + 16 * u;
            size_t g = (size_t)(kt * 128 + r) * rs + lf * 4;
            float4 kv = *(const float4*)&kbase[g];
            KsPT[(lf * 4 + 0) * 132 + r] = kv.x;
            KsPT[(lf * 4 + 1) * 132 + r] = kv.y;
            KsPT[(lf * 4 + 2) * 132 + r] = kv.z;
            KsPT[(lf * 4 + 3) * 132 + r] = kv.w;
            float4 vv = *(const float4*)&vbase[g];
            *(float4*)&Vs[r * 68 + lf * 4] = vv;
        }
        __syncthreads();

        // S = Q @ K^T (128x128x64)
        float s[8][8] = {};
        #pragma unroll
        for (int d = 0; d < 64; ++d) {
            float4 q0 = *(const float4*)&Qs[d * 132 + ty * 8];
            float4 q1 = *(const float4*)&Qs[d * 132 + ty * 8 + 4];
            float4 k0 = *(const float4*)&KsPT[d * 132 + tx * 8];
            float4 k1 = *(const float4*)&KsPT[d * 132 + tx * 8 + 4];
            float a[8] = {q0.x, q0.y, q0.z, q0.w, q1.x, q1.y, q1.z, q1.w};
            float kk[8] = {k0.x, k0.y, k0.z, k0.w, k1.x, k1.y, k1.z, k1.w};
            #pragma unroll
            for (int i = 0; i < 8; ++i)
                #pragma unroll
                for (int j = 0; j < 8; ++j)
                    s[i][j] = fmaf(a[i], kk[j], s[i][j]);
        }

        #pragma unroll
        for (int i = 0; i < 8; ++i)
            #pragma unroll
            for (int j = 0; j < 8; ++j)
                s[i][j] *= scale;

        if (kt == qt) {
            #pragma unroll
            for (int i = 0; i < 8; ++i)
                #pragma unroll
                for (int j = 0; j < 8; ++j)
                    if (tx * 8 + j > ty * 8 + i) s[i][j] = -1e30f;
        }

        // online softmax across 16 tx lanes
        float mt[8];
        #pragma unroll
        for (int i = 0; i < 8; ++i) {
            float m01 = fmaxf(s[i][0], s[i][1]);
            float m23 = fmaxf(s[i][2], s[i][3]);
            float m45 = fmaxf(s[i][4], s[i][5]);
            float m67 = fmaxf(s[i][6], s[i][7]);
            mt[i] = fmaxf(fmaxf(m01, m23), fmaxf(m45, m67));
        }
        #pragma unroll
        for (int off = 8; off > 0; off >>= 1)
            #pragma unroll
            for (int i = 0; i < 8; ++i)
                mt[i] = fmaxf(mt[i], __shfl_xor_sync(0xffffffffu, mt[i], off, 32));

        float rsum[8], corr[8];
        #pragma unroll
        for (int i = 0; i < 8; ++i) {
            float m_new = fmaxf(m_prev[i], mt[i]);
            float rsi = 0.f;
            #pragma unroll
            for (int j = 0; j < 8; ++j) {
                s[i][j] = __expf(s[i][j] - m_new);   // s becomes p
                rsi += s[i][j];
            }
            rsum[i] = rsi;
            corr[i] = __expf(m_prev[i] - m_new);
            m_prev[i] = m_new;
        }
        #pragma unroll
        for (int off = 8; off > 0; off >>= 1)
            #pragma unroll
            for (int i = 0; i < 8; ++i)
                rsum[i] += __shfl_xor_sync(0xffffffffu, rsum[i], off, 32);

        #pragma unroll
        for (int i = 0; i < 8; ++i) {
            l_run[i] = l_run[i] * corr[i] + rsum[i];
            o[i][0] *= corr[i]; o[i][1] *= corr[i];
            o[i][2] *= corr[i]; o[i][3] *= corr[i];
        }

        __syncthreads();  // all done reading Ks (PT overwrites it)

        // write P transposed, swizzled: PT[s][r]
        {
            const int m4 = (tx & 7) * 4;  // ((s>>3)&7)*4 with s = tx*8+j
            #pragma unroll
            for (int j = 0; j < 8; ++j) {
                int scol = tx * 8 + j;
                float4 v0 = make_float4(s[0][j], s[1][j], s[2][j], s[3][j]);
                float4 v1 = make_float4(s[4][j], s[5][j], s[6][j], s[7][j]);
                *(float4*)&KsPT[scol * 128 + ((ty * 8) ^ m4)]     = v0;
                *(float4*)&KsPT[scol * 128 + ((ty * 8 + 4) ^ m4)] = v1;
            }
        }
        __syncthreads();

        // O += P @ V (128x64x128)
        #pragma unroll 8
        for (int sidx = 0; sidx < 128; ++sidx) {
            int m4 = ((sidx >> 3) & 7) * 4;
            float4 p0 = *(const float4*)&KsPT[sidx * 128 + ((ty * 8) ^ m4)];
            float4 p1 = *(const float4*)&KsPT[sidx * 128 + ((ty * 8 + 4) ^ m4)];
            float4 vv = *(const float4*)&Vs[sidx * 68 + tx * 4];
            float a[8] = {p0.x, p0.y, p0.z, p0.w, p1.x, p1.y, p1.z, p1.w};
            #pragma unroll
            for (int i = 0; i < 8; ++i) {
                o[i][0] = fmaf(a[i], vv.x, o[i][0]);
                o[i][1] = fmaf(a[i], vv.y, o[i][1]);
                o[i][2] = fmaf(a[i], vv.z, o[i][2]);
                o[i][3] = fmaf(a[i], vv.w, o[i][3]);
            }
        }
    }

    // epilogue
    #pragma unroll
    for (int i = 0; i < 8; ++i) {
        int row = qt * 128 + ty * 8 + i;
        float inv = 1.0f / l_run[i];
        float4 ov;
        ov.x = o[i][0] * inv;
        ov.y = o[i][1] * inv;
        ov.z = o[i][2] * inv;
        ov.w = o[i][3] * inv;
        *(float4*)&out[((size_t)b * TT + row) * DD + h * DKK + tx * 4] = ov;
    }
}

// ---------------------------------------------------------------------------
extern "C" void kernel_launch(void* const* d_in, const int* in_sizes, int n_in,
                              void* d_out, int out_size)
{
    const float* x      = (const float*)d_in[0];
    const float* W_qkv  = (const float*)d_in[1];
    const float* b_qkv  = (const float*)d_in[2];
    const float* W_proj = (const float*)d_in[3];
    const float* b_proj = (const float*)d_in[4];
    float* out = (float*)d_out;

    float* qkv_scratch;
    float* attn_scratch;
    cudaGetSymbolAddress((void**)&qkv_scratch, g_qkv);
    cudaGetSymbolAddress((void**)&attn_scratch, g_attn);

    // 1) QKV projection: [8192,768] @ [768,2304] + bias
    {
        dim3 grid(THREEDD / 128, MROWS / 128);
        sgemm_bias_128<<<grid, 256>>>(x, W_qkv, b_qkv, qkv_scratch, THREEDD, DD);
    }

    // 2) Causal flash attention
    {
        const int smem = (8448 + 16384 + 8704) * (int)sizeof(float);  // 134144
        cudaFuncSetAttribute(attn_kernel,
                             cudaFuncAttributeMaxDynamicSharedMemorySize, smem);
        dim3 grid(TT / 128, HH, BB);
        attn_kernel<<<grid, 256, smem>>>(qkv_scratch, attn_scratch);
    }

    // 3) Output projection: [8192,768] @ [768,768] + bias
    {
        dim3 grid(DD / 128, MROWS / 128);
        sgemm_bias_128<<<grid, 256>>>(attn_scratch, W_proj, b_proj, out, DD, DD);
    }
}

// round 6
// speedup vs baseline: 2.4939x; 2.2050x over previous
#include <cuda_runtime.h>
#include <math.h>
#include <stdint.h>

#define BB 2
#define TT 4096
#define DD 768
#define HH 12
#define DKK 64
#define MROWS (BB*TT)          // 8192
#define THREEDD (3*DD)         // 2304

__device__ float g_qkv[(size_t)MROWS * THREEDD];   // [8192, 2304]
__device__ float g_attn[(size_t)MROWS * DD];       // [8192, 768]

__device__ __forceinline__ uint32_t f2tf32(float x) {
    uint32_t r;
    asm("cvt.rna.tf32.f32 %0, %1;" : "=r"(r) : "f"(x));
    return r;
}

__device__ __forceinline__ void mma_tf32(float* c,
    uint32_t a0, uint32_t a1, uint32_t a2, uint32_t a3,
    uint32_t b0, uint32_t b1)
{
    asm volatile(
        "mma.sync.aligned.m16n8k8.row.col.f32.tf32.tf32.f32 "
        "{%0,%1,%2,%3}, {%4,%5,%6,%7}, {%8,%9}, {%0,%1,%2,%3};"
        : "+f"(c[0]), "+f"(c[1]), "+f"(c[2]), "+f"(c[3])
        : "r"(a0), "r"(a1), "r"(a2), "r"(a3), "r"(b0), "r"(b1));
}

// ---------------------------------------------------------------------------
// TF32 tensor-core SGEMM + bias: C[M,N] = A[M,K] @ W[K,N] + bias[N]
// 128x128 tile, BK=32, 256 threads (8 warps, 2x4 warp grid, 64x32 warp tile).
// Double-buffered dynamic smem. Strides of 136 floats => conflict-free frags.
// ---------------------------------------------------------------------------
#define GSTR 136
#define GASZ (32 * GSTR)

__global__ __launch_bounds__(256, 2) void sgemm_tf32(
    const float* __restrict__ A, const float* __restrict__ W,
    const float* __restrict__ bias, float* __restrict__ C,
    int Ndim, int Kdim)
{
    extern __shared__ __align__(16) float smem[];
    float* AsB = smem;              // 2 * GASZ
    float* WsB = smem + 2 * GASZ;   // 2 * GASZ

    const int tid  = threadIdx.x;
    const int lane = tid & 31;
    const int wid  = tid >> 5;
    const int g    = lane >> 2;     // group id (row within fragment)
    const int tig  = lane & 3;      // thread in group
    const int wm   = (wid >> 2) * 64;
    const int wn   = (wid & 3) * 32;
    const int m0   = blockIdx.y * 128;
    const int n0   = blockIdx.x * 128;

    // A fill mapping: m = tid>>1, k half = (tid&1)*16, 4 float4 along k
    const int ar  = tid >> 1;
    const int aks = (tid & 1) * 16;
    // W fill mapping: row = tid>>5 (+8q), col4 = (tid&31)*4
    const int wr = tid >> 5;
    const int wc = (tid & 31) * 4;

    const float* Aptr = A + (size_t)(m0 + ar) * Kdim + aks;
    const float* Wptr = W + (size_t)wr * Ndim + n0 + wc;

    float4 Aq[4], Wq[4];
    #pragma unroll
    for (int q = 0; q < 4; ++q) {
        Aq[q] = *(const float4*)(Aptr + q * 4);
        Wq[q] = *(const float4*)(Wptr + (size_t)(8 * q) * Ndim);
    }
    {
        float* as = AsB;
        float* ws = WsB;
        #pragma unroll
        for (int q = 0; q < 4; ++q) {
            const float* v = (const float*)&Aq[q];
            #pragma unroll
            for (int j = 0; j < 4; ++j)
                as[(aks + q * 4 + j) * GSTR + ar] = __uint_as_float(f2tf32(v[j]));
            float4 wv = Wq[q];
            wv.x = __uint_as_float(f2tf32(wv.x));
            wv.y = __uint_as_float(f2tf32(wv.y));
            wv.z = __uint_as_float(f2tf32(wv.z));
            wv.w = __uint_as_float(f2tf32(wv.w));
            *(float4*)&ws[(wr + 8 * q) * GSTR + wc] = wv;
        }
    }
    __syncthreads();

    float acc[4][4][4] = {};
    const int nk = Kdim >> 5;   // BK=32

    for (int kb = 0; kb < nk; ++kb) {
        const float* as = AsB + (kb & 1) * GASZ;
        const float* ws = WsB + (kb & 1) * GASZ;

        if (kb + 1 < nk) {
            const float* Ap = Aptr + (size_t)(kb + 1) * 32;
            const float* Wp = Wptr + (size_t)(kb + 1) * 32 * Ndim;
            #pragma unroll
            for (int q = 0; q < 4; ++q) {
                Aq[q] = *(const float4*)(Ap + q * 4);
                Wq[q] = *(const float4*)(Wp + (size_t)(8 * q) * Ndim);
            }
        }

        #pragma unroll
        for (int ks = 0; ks < 4; ++ks) {
            const int k0 = ks * 8;
            uint32_t af[4][4];
            #pragma unroll
            for (int mi = 0; mi < 4; ++mi) {
                const int m = wm + mi * 16;
                af[mi][0] = __float_as_uint(as[(k0 + tig) * GSTR + m + g]);
                af[mi][1] = __float_as_uint(as[(k0 + tig) * GSTR + m + g + 8]);
                af[mi][2] = __float_as_uint(as[(k0 + tig + 4) * GSTR + m + g]);
                af[mi][3] = __float_as_uint(as[(k0 + tig + 4) * GSTR + m + g + 8]);
            }
            #pragma unroll
            for (int ni = 0; ni < 4; ++ni) {
                const int n = wn + ni * 8;
                uint32_t b0 = __float_as_uint(ws[(k0 + tig) * GSTR + n + g]);
                uint32_t b1 = __float_as_uint(ws[(k0 + tig + 4) * GSTR + n + g]);
                #pragma unroll
                for (int mi = 0; mi < 4; ++mi)
                    mma_tf32(acc[mi][ni], af[mi][0], af[mi][1], af[mi][2], af[mi][3], b0, b1);
            }
        }

        if (kb + 1 < nk) {
            float* asn = AsB + ((kb + 1) & 1) * GASZ;
            float* wsn = WsB + ((kb + 1) & 1) * GASZ;
            #pragma unroll
            for (int q = 0; q < 4; ++q) {
                const float* v = (const float*)&Aq[q];
                #pragma unroll
                for (int j = 0; j < 4; ++j)
                    asn[(aks + q * 4 + j) * GSTR + ar] = __uint_as_float(f2tf32(v[j]));
                float4 wv = Wq[q];
                wv.x = __uint_as_float(f2tf32(wv.x));
                wv.y = __uint_as_float(f2tf32(wv.y));
                wv.z = __uint_as_float(f2tf32(wv.z));
                wv.w = __uint_as_float(f2tf32(wv.w));
                *(float4*)&wsn[(wr + 8 * q) * GSTR + wc] = wv;
            }
        }
        __syncthreads();
    }

    // epilogue
    #pragma unroll
    for (int mi = 0; mi < 4; ++mi) {
        #pragma unroll
        for (int ni = 0; ni < 4; ++ni) {
            const int row = m0 + wm + mi * 16 + g;
            const int col = n0 + wn + ni * 8 + 2 * tig;
            float bx = bias[col], by = bias[col + 1];
            float2 o0 = make_float2(acc[mi][ni][0] + bx, acc[mi][ni][1] + by);
            float2 o1 = make_float2(acc[mi][ni][2] + bx, acc[mi][ni][3] + by);
            *(float2*)&C[(size_t)row * Ndim + col] = o0;
            *(float2*)&C[(size_t)(row + 8) * Ndim + col] = o1;
        }
    }
}

// ---------------------------------------------------------------------------
// Causal flash attention with tf32 mma. Br=128, Bc=64, 256 threads (8 warps),
// each warp owns 16 Q rows. smem (floats):
//   Qs [64][136]  Q transposed (dk-major)      8704
//   Ks [64][68]   K natural [key][dk]          4352
//   Vs [64][72]   V natural [key][dk]          4608
//   Ps [128][68]  P [qrow][key]                8704
// ---------------------------------------------------------------------------
__global__ __launch_bounds__(256, 1) void attn_tf32(
    const float* __restrict__ qkv, float* __restrict__ out)
{
    extern __shared__ __align__(16) float sm[];
    float* Qs = sm;                         // 64*136
    float* Ks = sm + 64 * 136;              // 64*68
    float* Vs = sm + 64 * 136 + 64 * 68;    // 64*72
    float* Ps = sm + 64 * 136 + 64 * 68 + 64 * 72;  // 128*68

    const int tid  = threadIdx.x;
    const int lane = tid & 31;
    const int wid  = tid >> 5;
    const int g    = lane >> 2;
    const int tig  = lane & 3;
    const int qt = (int)gridDim.x - 1 - (int)blockIdx.x;  // heavy tiles first
    const int h  = blockIdx.y;
    const int b  = blockIdx.z;

    const size_t rs = THREEDD;
    const float* qbase = qkv + (size_t)b * TT * rs + h * DKK;
    const float* kbase = qbase + DD;
    const float* vbase = qbase + 2 * DD;

    // Load Q tile transposed: Qs[dk][r]
    {
        const int r  = tid >> 1;
        const int dq = (tid & 1) * 8;
        #pragma unroll
        for (int q = 0; q < 8; ++q) {
            const int d = (dq + q) * 4;
            float4 v = *(const float4*)&qbase[(size_t)(qt * 128 + r) * rs + d];
            Qs[(d + 0) * 136 + r] = __uint_as_float(f2tf32(v.x));
            Qs[(d + 1) * 136 + r] = __uint_as_float(f2tf32(v.y));
            Qs[(d + 2) * 136 + r] = __uint_as_float(f2tf32(v.z));
            Qs[(d + 3) * 136 + r] = __uint_as_float(f2tf32(v.w));
        }
    }

    float oacc[8][4] = {};
    float m_prev[2] = {-1e30f, -1e30f};
    float l_run[2]  = {0.f, 0.f};
    const float scale = 0.125f;  // 1/sqrt(64)
    const int wrow = wid * 16;   // warp's Q-row base within tile

    const int nkt = 2 * qt + 2;  // number of 64-key tiles

    for (int kt = 0; kt < nkt; ++kt) {
        __syncthreads();  // previous iter done with Ks/Vs
        {
            const int key = tid >> 2;
            const int c4  = tid & 3;
            #pragma unroll
            for (int q = 0; q < 4; ++q) {
                const int d = (c4 * 4 + q) * 4;
                size_t gidx = (size_t)(kt * 64 + key) * rs + d;
                float4 kv = *(const float4*)&kbase[gidx];
                kv.x = __uint_as_float(f2tf32(kv.x));
                kv.y = __uint_as_float(f2tf32(kv.y));
                kv.z = __uint_as_float(f2tf32(kv.z));
                kv.w = __uint_as_float(f2tf32(kv.w));
                *(float4*)&Ks[key * 68 + d] = kv;
                float4 vv = *(const float4*)&vbase[gidx];
                vv.x = __uint_as_float(f2tf32(vv.x));
                vv.y = __uint_as_float(f2tf32(vv.y));
                vv.z = __uint_as_float(f2tf32(vv.z));
                vv.w = __uint_as_float(f2tf32(vv.w));
                *(float4*)&Vs[key * 72 + d] = vv;
            }
        }
        __syncthreads();

        // S = Q @ K^T  (warp: 16 x 64, k=64)
        float sfrag[8][4] = {};
        #pragma unroll
        for (int ks = 0; ks < 8; ++ks) {
            const int k0 = ks * 8;
            uint32_t a0 = __float_as_uint(Qs[(k0 + tig) * 136 + wrow + g]);
            uint32_t a1 = __float_as_uint(Qs[(k0 + tig) * 136 + wrow + g + 8]);
            uint32_t a2 = __float_as_uint(Qs[(k0 + tig + 4) * 136 + wrow + g]);
            uint32_t a3 = __float_as_uint(Qs[(k0 + tig + 4) * 136 + wrow + g + 8]);
            #pragma unroll
            for (int nt = 0; nt < 8; ++nt) {
                uint32_t b0 = __float_as_uint(Ks[(nt * 8 + g) * 68 + k0 + tig]);
                uint32_t b1 = __float_as_uint(Ks[(nt * 8 + g) * 68 + k0 + tig + 4]);
                mma_tf32(sfrag[nt], a0, a1, a2, a3, b0, b1);
            }
        }

        // scale + causal mask
        const int qrow0 = qt * 128 + wrow + g;
        const int qrow1 = qrow0 + 8;
        #pragma unroll
        for (int nt = 0; nt < 8; ++nt) {
            #pragma unroll
            for (int c = 0; c < 4; ++c) sfrag[nt][c] *= scale;
        }
        if (kt >= 2 * qt) {
            #pragma unroll
            for (int nt = 0; nt < 8; ++nt) {
                const int kc = kt * 64 + nt * 8 + 2 * tig;
                if (kc > qrow0)     sfrag[nt][0] = -1e30f;
                if (kc + 1 > qrow0) sfrag[nt][1] = -1e30f;
                if (kc > qrow1)     sfrag[nt][2] = -1e30f;
                if (kc + 1 > qrow1) sfrag[nt][3] = -1e30f;
            }
        }

        // online softmax (2 rows per thread; 4 lanes per row)
        float mt0 = -1e30f, mt1 = -1e30f;
        #pragma unroll
        for (int nt = 0; nt < 8; ++nt) {
            mt0 = fmaxf(mt0, fmaxf(sfrag[nt][0], sfrag[nt][1]));
            mt1 = fmaxf(mt1, fmaxf(sfrag[nt][2], sfrag[nt][3]));
        }
        mt0 = fmaxf(mt0, __shfl_xor_sync(0xffffffffu, mt0, 1));
        mt0 = fmaxf(mt0, __shfl_xor_sync(0xffffffffu, mt0, 2));
        mt1 = fmaxf(mt1, __shfl_xor_sync(0xffffffffu, mt1, 1));
        mt1 = fmaxf(mt1, __shfl_xor_sync(0xffffffffu, mt1, 2));

        const float mn0 = fmaxf(m_prev[0], mt0);
        const float mn1 = fmaxf(m_prev[1], mt1);
        const float corr0 = __expf(m_prev[0] - mn0);
        const float corr1 = __expf(m_prev[1] - mn1);
        m_prev[0] = mn0; m_prev[1] = mn1;

        float rs0 = 0.f, rs1 = 0.f;
        #pragma unroll
        for (int nt = 0; nt < 8; ++nt) {
            sfrag[nt][0] = __expf(sfrag[nt][0] - mn0);
            sfrag[nt][1] = __expf(sfrag[nt][1] - mn0);
            sfrag[nt][2] = __expf(sfrag[nt][2] - mn1);
            sfrag[nt][3] = __expf(sfrag[nt][3] - mn1);
            rs0 += sfrag[nt][0] + sfrag[nt][1];
            rs1 += sfrag[nt][2] + sfrag[nt][3];
        }
        rs0 += __shfl_xor_sync(0xffffffffu, rs0, 1);
        rs0 += __shfl_xor_sync(0xffffffffu, rs0, 2);
        rs1 += __shfl_xor_sync(0xffffffffu, rs1, 1);
        rs1 += __shfl_xor_sync(0xffffffffu, rs1, 2);
        l_run[0] = l_run[0] * corr0 + rs0;
        l_run[1] = l_run[1] * corr1 + rs1;

        #pragma unroll
        for (int nt = 0; nt < 8; ++nt) {
            oacc[nt][0] *= corr0; oacc[nt][1] *= corr0;
            oacc[nt][2] *= corr1; oacc[nt][3] *= corr1;
        }

        __syncthreads();  // previous PV done reading Ps
        #pragma unroll
        for (int nt = 0; nt < 8; ++nt) {
            const int c = nt * 8 + 2 * tig;
            *(float2*)&Ps[(wrow + g) * 68 + c]     = make_float2(sfrag[nt][0], sfrag[nt][1]);
            *(float2*)&Ps[(wrow + g + 8) * 68 + c] = make_float2(sfrag[nt][2], sfrag[nt][3]);
        }
        __syncthreads();

        // O += P @ V  (warp: 16 x 64, k=64)
        #pragma unroll
        for (int ks = 0; ks < 8; ++ks) {
            const int k0 = ks * 8;
            uint32_t a0 = __float_as_uint(Ps[(wrow + g) * 68 + k0 + tig]);
            uint32_t a1 = __float_as_uint(Ps[(wrow + g + 8) * 68 + k0 + tig]);
            uint32_t a2 = __float_as_uint(Ps[(wrow + g) * 68 + k0 + tig + 4]);
            uint32_t a3 = __float_as_uint(Ps[(wrow + g + 8) * 68 + k0 + tig + 4]);
            #pragma unroll
            for (int nt = 0; nt < 8; ++nt) {
                uint32_t b0 = __float_as_uint(Vs[(k0 + tig) * 72 + nt * 8 + g]);
                uint32_t b1 = __float_as_uint(Vs[(k0 + tig + 4) * 72 + nt * 8 + g]);
                mma_tf32(oacc[nt], a0, a1, a2, a3, b0, b1);
            }
        }
    }

    // epilogue: out[b, qt*128 + r, h*64 + c] = o / l
    const float inv0 = 1.0f / l_run[0];
    const float inv1 = 1.0f / l_run[1];
    const int r0 = qt * 128 + wrow + g;
    #pragma unroll
    for (int nt = 0; nt < 8; ++nt) {
        const int c = h * DKK + nt * 8 + 2 * tig;
        *(float2*)&out[((size_t)b * TT + r0) * DD + c] =
            make_float2(oacc[nt][0] * inv0, oacc[nt][1] * inv0);
        *(float2*)&out[((size_t)b * TT + r0 + 8) * DD + c] =
            make_float2(oacc[nt][2] * inv1, oacc[nt][3] * inv1);
    }
}

// ---------------------------------------------------------------------------
extern "C" void kernel_launch(void* const* d_in, const int* in_sizes, int n_in,
                              void* d_out, int out_size)
{
    const float* x      = (const float*)d_in[0];
    const float* W_qkv  = (const float*)d_in[1];
    const float* b_qkv  = (const float*)d_in[2];
    const float* W_proj = (const float*)d_in[3];
    const float* b_proj = (const float*)d_in[4];
    float* out = (float*)d_out;

    float* qkv_scratch;
    float* attn_scratch;
    cudaGetSymbolAddress((void**)&qkv_scratch, g_qkv);
    cudaGetSymbolAddress((void**)&attn_scratch, g_attn);

    const int gemm_smem = 4 * GASZ * (int)sizeof(float);   // 69632
    cudaFuncSetAttribute(sgemm_tf32,
                         cudaFuncAttributeMaxDynamicSharedMemorySize, gemm_smem);

    // 1) QKV projection: [8192,768] @ [768,2304] + bias
    {
        dim3 grid(THREEDD / 128, MROWS / 128);
        sgemm_tf32<<<grid, 256, gemm_smem>>>(x, W_qkv, b_qkv, qkv_scratch,
                                             THREEDD, DD);
    }

    // 2) Causal flash attention
    {
        const int smem = (64 * 136 + 64 * 68 + 64 * 72 + 128 * 68) * (int)sizeof(float);
        cudaFuncSetAttribute(attn_tf32,
                             cudaFuncAttributeMaxDynamicSharedMemorySize, smem);
        dim3 grid(TT / 128, HH, BB);
        attn_tf32<<<grid, 256, smem>>>(qkv_scratch, attn_scratch);
    }

    // 3) Output projection: [8192,768] @ [768,768] + bias
    {
        dim3 grid(DD / 128, MROWS / 128);
        sgemm_tf32<<<grid, 256, gemm_smem>>>(attn_scratch, W_proj, b_proj, out,
                                             DD, DD);
    }
}

// round 7
// speedup vs baseline: 2.5184x; 1.0098x over previous
#include <cuda_runtime.h>
#include <math.h>
#include <stdint.h>

#define BB 2
#define TT 4096
#define DD 768
#define HH 12
#define DKK 64
#define MROWS (BB*TT)          // 8192
#define THREEDD (3*DD)         // 2304

__device__ float g_qkv[(size_t)MROWS * THREEDD];   // [8192, 2304]
__device__ float g_attn[(size_t)MROWS * DD];       // [8192, 768]

__device__ __forceinline__ uint32_t f2tf32(float x) {
    uint32_t r;
    asm("cvt.rna.tf32.f32 %0, %1;" : "=r"(r) : "f"(x));
    return r;
}

__device__ __forceinline__ void mma_tf32(float* c,
    uint32_t a0, uint32_t a1, uint32_t a2, uint32_t a3,
    uint32_t b0, uint32_t b1)
{
    asm volatile(
        "mma.sync.aligned.m16n8k8.row.col.f32.tf32.tf32.f32 "
        "{%0,%1,%2,%3}, {%4,%5,%6,%7}, {%8,%9}, {%0,%1,%2,%3};"
        : "+f"(c[0]), "+f"(c[1]), "+f"(c[2]), "+f"(c[3])
        : "r"(a0), "r"(a1), "r"(a2), "r"(a3), "r"(b0), "r"(b1));
}

// ---------------------------------------------------------------------------
// TF32 tensor-core SGEMM + bias: C[M,N] = A[M,K] @ W[K,N] + bias[N]
// 128x128 tile, BK=32, 256 threads (8 warps, 2x4 warp grid, 64x32 warp tile).
// Double-buffered dynamic smem. Strides of 136 floats => conflict-free frags.
// ---------------------------------------------------------------------------
#define GSTR 136
#define GASZ (32 * GSTR)

__global__ __launch_bounds__(256, 2) void sgemm_tf32(
    const float* __restrict__ A, const float* __restrict__ W,
    const float* __restrict__ bias, float* __restrict__ C,
    int Ndim, int Kdim)
{
    extern __shared__ __align__(16) float smem[];
    float* AsB = smem;              // 2 * GASZ
    float* WsB = smem + 2 * GASZ;   // 2 * GASZ

    const int tid  = threadIdx.x;
    const int lane = tid & 31;
    const int wid  = tid >> 5;
    const int g    = lane >> 2;     // group id (row within fragment)
    const int tig  = lane & 3;      // thread in group
    const int wm   = (wid >> 2) * 64;
    const int wn   = (wid & 3) * 32;
    const int m0   = blockIdx.y * 128;
    const int n0   = blockIdx.x * 128;

    // A fill mapping: m = tid>>1, k half = (tid&1)*16, 4 float4 along k
    const int ar  = tid >> 1;
    const int aks = (tid & 1) * 16;
    // W fill mapping: row = tid>>5 (+8q), col4 = (tid&31)*4
    const int wr = tid >> 5;
    const int wc = (tid & 31) * 4;

    const float* Aptr = A + (size_t)(m0 + ar) * Kdim + aks;
    const float* Wptr = W + (size_t)wr * Ndim + n0 + wc;

    float4 Aq[4], Wq[4];
    #pragma unroll
    for (int q = 0; q < 4; ++q) {
        Aq[q] = *(const float4*)(Aptr + q * 4);
        Wq[q] = *(const float4*)(Wptr + (size_t)(8 * q) * Ndim);
    }
    {
        float* as = AsB;
        float* ws = WsB;
        #pragma unroll
        for (int q = 0; q < 4; ++q) {
            const float* v = (const float*)&Aq[q];
            #pragma unroll
            for (int j = 0; j < 4; ++j)
                as[(aks + q * 4 + j) * GSTR + ar] = __uint_as_float(f2tf32(v[j]));
            float4 wv = Wq[q];
            wv.x = __uint_as_float(f2tf32(wv.x));
            wv.y = __uint_as_float(f2tf32(wv.y));
            wv.z = __uint_as_float(f2tf32(wv.z));
            wv.w = __uint_as_float(f2tf32(wv.w));
            *(float4*)&ws[(wr + 8 * q) * GSTR + wc] = wv;
        }
    }
    __syncthreads();

    float acc[4][4][4] = {};
    const int nk = Kdim >> 5;   // BK=32

    for (int kb = 0; kb < nk; ++kb) {
        const float* as = AsB + (kb & 1) * GASZ;
        const float* ws = WsB + (kb & 1) * GASZ;

        if (kb + 1 < nk) {
            const float* Ap = Aptr + (size_t)(kb + 1) * 32;
            const float* Wp = Wptr + (size_t)(kb + 1) * 32 * Ndim;
            #pragma unroll
            for (int q = 0; q < 4; ++q) {
                Aq[q] = *(const float4*)(Ap + q * 4);
                Wq[q] = *(const float4*)(Wp + (size_t)(8 * q) * Ndim);
            }
        }

        #pragma unroll
        for (int ks = 0; ks < 4; ++ks) {
            const int k0 = ks * 8;
            uint32_t af[4][4];
            #pragma unroll
            for (int mi = 0; mi < 4; ++mi) {
                const int m = wm + mi * 16;
                af[mi][0] = __float_as_uint(as[(k0 + tig) * GSTR + m + g]);
                af[mi][1] = __float_as_uint(as[(k0 + tig) * GSTR + m + g + 8]);
                af[mi][2] = __float_as_uint(as[(k0 + tig + 4) * GSTR + m + g]);
                af[mi][3] = __float_as_uint(as[(k0 + tig + 4) * GSTR + m + g + 8]);
            }
            #pragma unroll
            for (int ni = 0; ni < 4; ++ni) {
                const int n = wn + ni * 8;
                uint32_t b0 = __float_as_uint(ws[(k0 + tig) * GSTR + n + g]);
                uint32_t b1 = __float_as_uint(ws[(k0 + tig + 4) * GSTR + n + g]);
                #pragma unroll
                for (int mi = 0; mi < 4; ++mi)
                    mma_tf32(acc[mi][ni], af[mi][0], af[mi][1], af[mi][2], af[mi][3], b0, b1);
            }
        }

        if (kb + 1 < nk) {
            float* asn = AsB + ((kb + 1) & 1) * GASZ;
            float* wsn = WsB + ((kb + 1) & 1) * GASZ;
            #pragma unroll
            for (int q = 0; q < 4; ++q) {
                const float* v = (const float*)&Aq[q];
                #pragma unroll
                for (int j = 0; j < 4; ++j)
                    asn[(aks + q * 4 + j) * GSTR + ar] = __uint_as_float(f2tf32(v[j]));
                float4 wv = Wq[q];
                wv.x = __uint_as_float(f2tf32(wv.x));
                wv.y = __uint_as_float(f2tf32(wv.y));
                wv.z = __uint_as_float(f2tf32(wv.z));
                wv.w = __uint_as_float(f2tf32(wv.w));
                *(float4*)&wsn[(wr + 8 * q) * GSTR + wc] = wv;
            }
        }
        __syncthreads();
    }

    // epilogue
    #pragma unroll
    for (int mi = 0; mi < 4; ++mi) {
        #pragma unroll
        for (int ni = 0; ni < 4; ++ni) {
            const int row = m0 + wm + mi * 16 + g;
            const int col = n0 + wn + ni * 8 + 2 * tig;
            float bx = bias[col], by = bias[col + 1];
            float2 o0 = make_float2(acc[mi][ni][0] + bx, acc[mi][ni][1] + by);
            float2 o1 = make_float2(acc[mi][ni][2] + bx, acc[mi][ni][3] + by);
            *(float2*)&C[(size_t)row * Ndim + col] = o0;
            *(float2*)&C[(size_t)(row + 8) * Ndim + col] = o1;
        }
    }
}

// ---------------------------------------------------------------------------
// Causal flash attention with tf32 mma. Br=128, Bc=64, 256 threads (8 warps),
// each warp owns 16 Q rows. smem (floats):
//   Qs [64][136]  Q transposed (dk-major)      8704
//   Ks [64][68]   K natural [key][dk]          4352
//   Vs [64][72]   V natural [key][dk]          4608
//   Ps [128][68]  P [qrow][key]                8704
// ---------------------------------------------------------------------------
__global__ __launch_bounds__(256, 1) void attn_tf32(
    const float* __restrict__ qkv, float* __restrict__ out)
{
    extern __shared__ __align__(16) float sm[];
    float* Qs = sm;                         // 64*136
    float* Ks = sm + 64 * 136;              // 64*68
    float* Vs = sm + 64 * 136 + 64 * 68;    // 64*72
    float* Ps = sm + 64 * 136 + 64 * 68 + 64 * 72;  // 128*68

    const int tid  = threadIdx.x;
    const int lane = tid & 31;
    const int wid  = tid >> 5;
    const int g    = lane >> 2;
    const int tig  = lane & 3;
    const int qt = (int)gridDim.x - 1 - (int)blockIdx.x;  // heavy tiles first
    const int h  = blockIdx.y;
    const int b  = blockIdx.z;

    const size_t rs = THREEDD;
    const float* qbase = qkv + (size_t)b * TT * rs + h * DKK;
    const float* kbase = qbase + DD;
    const float* vbase = qbase + 2 * DD;

    // Load Q tile transposed: Qs[dk][r]
    {
        const int r  = tid >> 1;
        const int dq = (tid & 1) * 8;
        #pragma unroll
        for (int q = 0; q < 8; ++q) {
            const int d = (dq + q) * 4;
            float4 v = *(const float4*)&qbase[(size_t)(qt * 128 + r) * rs + d];
            Qs[(d + 0) * 136 + r] = __uint_as_float(f2tf32(v.x));
            Qs[(d + 1) * 136 + r] = __uint_as_float(f2tf32(v.y));
            Qs[(d + 2) * 136 + r] = __uint_as_float(f2tf32(v.z));
            Qs[(d + 3) * 136 + r] = __uint_as_float(f2tf32(v.w));
        }
    }

    float oacc[8][4] = {};
    float m_prev[2] = {-1e30f, -1e30f};
    float l_run[2]  = {0.f, 0.f};
    const float scale = 0.125f;  // 1/sqrt(64)
    const int wrow = wid * 16;   // warp's Q-row base within tile

    const int nkt = 2 * qt + 2;  // number of 64-key tiles

    for (int kt = 0; kt < nkt; ++kt) {
        __syncthreads();  // previous iter done with Ks/Vs
        {
            const int key = tid >> 2;
            const int c4  = tid & 3;
            #pragma unroll
            for (int q = 0; q < 4; ++q) {
                const int d = (c4 * 4 + q) * 4;
                size_t gidx = (size_t)(kt * 64 + key) * rs + d;
                float4 kv = *(const float4*)&kbase[gidx];
                kv.x = __uint_as_float(f2tf32(kv.x));
                kv.y = __uint_as_float(f2tf32(kv.y));
                kv.z = __uint_as_float(f2tf32(kv.z));
                kv.w = __uint_as_float(f2tf32(kv.w));
                *(float4*)&Ks[key * 68 + d] = kv;
                float4 vv = *(const float4*)&vbase[gidx];
                vv.x = __uint_as_float(f2tf32(vv.x));
                vv.y = __uint_as_float(f2tf32(vv.y));
                vv.z = __uint_as_float(f2tf32(vv.z));
                vv.w = __uint_as_float(f2tf32(vv.w));
                *(float4*)&Vs[key * 72 + d] = vv;
            }
        }
        __syncthreads();

        // S = Q @ K^T  (warp: 16 x 64, k=64)
        float sfrag[8][4] = {};
        #pragma unroll
        for (int ks = 0; ks < 8; ++ks) {
            const int k0 = ks * 8;
            uint32_t a0 = __float_as_uint(Qs[(k0 + tig) * 136 + wrow + g]);
            uint32_t a1 = __float_as_uint(Qs[(k0 + tig) * 136 + wrow + g + 8]);
            uint32_t a2 = __float_as_uint(Qs[(k0 + tig + 4) * 136 + wrow + g]);
            uint32_t a3 = __float_as_uint(Qs[(k0 + tig + 4) * 136 + wrow + g + 8]);
            #pragma unroll
            for (int nt = 0; nt < 8; ++nt) {
                uint32_t b0 = __float_as_uint(Ks[(nt * 8 + g) * 68 + k0 + tig]);
                uint32_t b1 = __float_as_uint(Ks[(nt * 8 + g) * 68 + k0 + tig + 4]);
                mma_tf32(sfrag[nt], a0, a1, a2, a3, b0, b1);
            }
        }

        // scale + causal mask
        const int qrow0 = qt * 128 + wrow + g;
        const int qrow1 = qrow0 + 8;
        #pragma unroll
        for (int nt = 0; nt < 8; ++nt) {
            #pragma unroll
            for (int c = 0; c < 4; ++c) sfrag[nt][c] *= scale;
        }
        if (kt >= 2 * qt) {
            #pragma unroll
            for (int nt = 0; nt < 8; ++nt) {
                const int kc = kt * 64 + nt * 8 + 2 * tig;
                if (kc > qrow0)     sfrag[nt][0] = -1e30f;
                if (kc + 1 > qrow0) sfrag[nt][1] = -1e30f;
                if (kc > qrow1)     sfrag[nt][2] = -1e30f;
                if (kc + 1 > qrow1) sfrag[nt][3] = -1e30f;
            }
        }

        // online softmax (2 rows per thread; 4 lanes per row)
        float mt0 = -1e30f, mt1 = -1e30f;
        #pragma unroll
        for (int nt = 0; nt < 8; ++nt) {
            mt0 = fmaxf(mt0, fmaxf(sfrag[nt][0], sfrag[nt][1]));
            mt1 = fmaxf(mt1, fmaxf(sfrag[nt][2], sfrag[nt][3]));
        }
        mt0 = fmaxf(mt0, __shfl_xor_sync(0xffffffffu, mt0, 1));
        mt0 = fmaxf(mt0, __shfl_xor_sync(0xffffffffu, mt0, 2));
        mt1 = fmaxf(mt1, __shfl_xor_sync(0xffffffffu, mt1, 1));
        mt1 = fmaxf(mt1, __shfl_xor_sync(0xffffffffu, mt1, 2));

        const float mn0 = fmaxf(m_prev[0], mt0);
        const float mn1 = fmaxf(m_prev[1], mt1);
        const float corr0 = __expf(m_prev[0] - mn0);
        const float corr1 = __expf(m_prev[1] - mn1);
        m_prev[0] = mn0; m_prev[1] = mn1;

        float rs0 = 0.f, rs1 = 0.f;
        #pragma unroll
        for (int nt = 0; nt < 8; ++nt) {
            sfrag[nt][0] = __expf(sfrag[nt][0] - mn0);
            sfrag[nt][1] = __expf(sfrag[nt][1] - mn0);
            sfrag[nt][2] = __expf(sfrag[nt][2] - mn1);
            sfrag[nt][3] = __expf(sfrag[nt][3] - mn1);
            rs0 += sfrag[nt][0] + sfrag[nt][1];
            rs1 += sfrag[nt][2] + sfrag[nt][3];
        }
        rs0 += __shfl_xor_sync(0xffffffffu, rs0, 1);
        rs0 += __shfl_xor_sync(0xffffffffu, rs0, 2);
        rs1 += __shfl_xor_sync(0xffffffffu, rs1, 1);
        rs1 += __shfl_xor_sync(0xffffffffu, rs1, 2);
        l_run[0] = l_run[0] * corr0 + rs0;
        l_run[1] = l_run[1] * corr1 + rs1;

        #pragma unroll
        for (int nt = 0; nt < 8; ++nt) {
            oacc[nt][0] *= corr0; oacc[nt][1] *= corr0;
            oacc[nt][2] *= corr1; oacc[nt][3] *= corr1;
        }

        __syncthreads();  // previous PV done reading Ps
        #pragma unroll
        for (int nt = 0; nt < 8; ++nt) {
            const int c = nt * 8 + 2 * tig;
            *(float2*)&Ps[(wrow + g) * 68 + c]     = make_float2(sfrag[nt][0], sfrag[nt][1]);
            *(float2*)&Ps[(wrow + g + 8) * 68 + c] = make_float2(sfrag[nt][2], sfrag[nt][3]);
        }
        __syncthreads();

        // O += P @ V  (warp: 16 x 64, k=64)
        #pragma unroll
        for (int ks = 0; ks < 8; ++ks) {
            const int k0 = ks * 8;
            uint32_t a0 = __float_as_uint(Ps[(wrow + g) * 68 + k0 + tig]);
            uint32_t a1 = __float_as_uint(Ps[(wrow + g + 8) * 68 + k0 + tig]);
            uint32_t a2 = __float_as_uint(Ps[(wrow + g) * 68 + k0 + tig + 4]);
            uint32_t a3 = __float_as_uint(Ps[(wrow + g + 8) * 68 + k0 + tig + 4]);
            #pragma unroll
            for (int nt = 0; nt < 8; ++nt) {
                uint32_t b0 = __float_as_uint(Vs[(k0 + tig) * 72 + nt * 8 + g]);
                uint32_t b1 = __float_as_uint(Vs[(k0 + tig + 4) * 72 + nt * 8 + g]);
                mma_tf32(oacc[nt], a0, a1, a2, a3, b0, b1);
            }
        }
    }

    // epilogue: out[b, qt*128 + r, h*64 + c] = o / l
    const float inv0 = 1.0f / l_run[0];
    const float inv1 = 1.0f / l_run[1];
    const int r0 = qt * 128 + wrow + g;
    #pragma unroll
    for (int nt = 0; nt < 8; ++nt) {
        const int c = h * DKK + nt * 8 + 2 * tig;
        *(float2*)&out[((size_t)b * TT + r0) * DD + c] =
            make_float2(oacc[nt][0] * inv0, oacc[nt][1] * inv0);
        *(float2*)&out[((size_t)b * TT + r0 + 8) * DD + c] =
            make_float2(oacc[nt][2] * inv1, oacc[nt][3] * inv1);
    }
}

// ---------------------------------------------------------------------------
extern "C" void kernel_launch(void* const* d_in, const int* in_sizes, int n_in,
                              void* d_out, int out_size)
{
    const float* x      = (const float*)d_in[0];
    const float* W_qkv  = (const float*)d_in[1];
    const float* b_qkv  = (const float*)d_in[2];
    const float* W_proj = (const float*)d_in[3];
    const float* b_proj = (const float*)d_in[4];
    float* out = (float*)d_out;

    float* qkv_scratch;
    float* attn_scratch;
    cudaGetSymbolAddress((void**)&qkv_scratch, g_qkv);
    cudaGetSymbolAddress((void**)&attn_scratch, g_attn);

    const int gemm_smem = 4 * GASZ * (int)sizeof(float);   // 69632
    cudaFuncSetAttribute(sgemm_tf32,
                         cudaFuncAttributeMaxDynamicSharedMemorySize, gemm_smem);

    // 1) QKV projection: [8192,768] @ [768,2304] + bias
    {
        dim3 grid(THREEDD / 128, MROWS / 128);
        sgemm_tf32<<<grid, 256, gemm_smem>>>(x, W_qkv, b_qkv, qkv_scratch,
                                             THREEDD, DD);
    }

    // 2) Causal flash attention
    {
        const int smem = (64 * 136 + 64 * 68 + 64 * 72 + 128 * 68) * (int)sizeof(float);
        cudaFuncSetAttribute(attn_tf32,
                             cudaFuncAttributeMaxDynamicSharedMemorySize, smem);
        dim3 grid(TT / 128, HH, BB);
        attn_tf32<<<grid, 256, smem>>>(qkv_scratch, attn_scratch);
    }

    // 3) Output projection: [8192,768] @ [768,768] + bias
    {
        dim3 grid(DD / 128, MROWS / 128);
        sgemm_tf32<<<grid, 256, gemm_smem>>>(attn_scratch, W_proj, b_proj, out,
                                             DD, DD);
    }
}